// round 1
// baseline (speedup 1.0000x reference)
#include <cuda_runtime.h>
#include <math.h>

#define MEM 2048
#define NV4 (MEM / 4)          // float4 per row = 512
#define ITERS (NV4 / 32)       // per-lane float4 iterations = 16

// Scratch (allocation-free: __device__ globals)
__device__ float g_sL[MEM];    // w[j] * m_left[j]
__device__ float g_sR[MEM];    // w[j] * m_right[j]
__device__ float g_pL[MEM];    // (ma @ lh)[j]
__device__ float g_pR[MEM];    // (ma @ rh)[j]
__device__ float g_la[MEM];
__device__ float g_ra[MEM];

__device__ __forceinline__ float warp_sum(float v) {
#pragma unroll
    for (int o = 16; o > 0; o >>= 1) v += __shfl_xor_sync(0xffffffffu, v, o);
    return v;
}

__device__ __forceinline__ float dot4(float4 a, float4 b) {
    return fmaf(a.x, b.x, fmaf(a.y, b.y, fmaf(a.z, b.z, a.w * b.w)));
}

// ---------------------------------------------------------------------------
// K1: attention scoring + hoisted ma matvecs.
// One warp per output row j. Reads Wh[j,:], Us[j,:], ma[j,:] exactly once.
// ---------------------------------------------------------------------------
__global__ void __launch_bounds__(128) k1_score(
    const float* __restrict__ lh, const float* __restrict__ rh,
    const float* __restrict__ S,  const float* __restrict__ w,
    const float* __restrict__ Wh_w, const float* __restrict__ Wh_b,
    const float* __restrict__ Us_w, const float* __restrict__ Us_b,
    const float* __restrict__ ma_w)
{
    const int warp = (blockIdx.x * blockDim.x + threadIdx.x) >> 5;
    const int lane = threadIdx.x & 31;
    if (warp >= MEM) return;

    const float4* __restrict__ Wh4 = (const float4*)Wh_w + (size_t)warp * NV4;
    const float4* __restrict__ Us4 = (const float4*)Us_w + (size_t)warp * NV4;
    const float4* __restrict__ ma4 = (const float4*)ma_w + (size_t)warp * NV4;
    const float4* __restrict__ lh4 = (const float4*)lh;
    const float4* __restrict__ rh4 = (const float4*)rh;
    const float4* __restrict__ S4  = (const float4*)S;

    float aWL = 0.f, aWR = 0.f, aUS = 0.f, aML = 0.f, aMR = 0.f;
#pragma unroll 8
    for (int i = 0; i < ITERS; i++) {
        const int idx = i * 32 + lane;
        float4 wv = Wh4[idx];
        float4 uv = Us4[idx];
        float4 mv = ma4[idx];
        float4 l  = lh4[idx];
        float4 r  = rh4[idx];
        float4 s  = S4[idx];
        aWL += dot4(wv, l);
        aWR += dot4(wv, r);
        aUS += dot4(uv, s);
        aML += dot4(mv, l);
        aMR += dot4(mv, r);
    }
    aWL = warp_sum(aWL);
    aWR = warp_sum(aWR);
    aUS = warp_sum(aUS);
    aML = warp_sum(aML);
    aMR = warp_sum(aMR);

    if (lane == 0) {
        const float base = Wh_b[warp] + Us_b[warp];
        const float mL = tanhf(aWL + aUS + base);
        const float mR = tanhf(aWR + aUS + base);
        const float wj = w[warp];
        g_sL[warp] = wj * mL;
        g_sR[warp] = wj * mR;
        g_pL[warp] = aML;
        g_pR[warp] = aMR;
    }
}

// ---------------------------------------------------------------------------
// K2: reduce scores -> alphas -> la/ra. Single block (tiny).
// ---------------------------------------------------------------------------
__global__ void __launch_bounds__(1024) k2_alpha(const float* __restrict__ ma_b)
{
    __shared__ float sL[1024];
    __shared__ float sR[1024];
    __shared__ float s_aL, s_aR;
    const int t = threadIdx.x;

    sL[t] = g_sL[t] + g_sL[t + 1024];
    sR[t] = g_sR[t] + g_sR[t + 1024];
    __syncthreads();
#pragma unroll
    for (int s = 512; s > 0; s >>= 1) {
        if (t < s) { sL[t] += sL[t + s]; sR[t] += sR[t + s]; }
        __syncthreads();
    }
    if (t == 0) {
        const float eL = sL[0], eR = sR[0];
        const float inv = 1.0f / (eL + eR);
        s_aL = eL * inv;
        s_aR = eR * inv;
    }
    __syncthreads();
    const float aL = s_aL, aR = s_aR;

#pragma unroll
    for (int j = t; j < MEM; j += 1024) {
        const float b = ma_b[j];
        g_la[j] = tanhf(fmaf(aL, g_pL[j], b));
        g_ra[j] = tanhf(fmaf(aR, g_pR[j], b));
    }
}

// ---------------------------------------------------------------------------
// K3: all 8 gate matvecs + LSTM combine. One warp per output element j.
// Reads row j of each of the 8 gate matrices, emits c[j], h[j] directly.
// ---------------------------------------------------------------------------
__global__ void __launch_bounds__(128) k3_gates(
    const float* __restrict__ lc, const float* __restrict__ rc,
    const float* __restrict__ ilh_w,  const float* __restrict__ ilh_b,
    const float* __restrict__ irh_w,  const float* __restrict__ irh_b,
    const float* __restrict__ lflh_w, const float* __restrict__ lflh_b,
    const float* __restrict__ lfrh_w, const float* __restrict__ lfrh_b,
    const float* __restrict__ rflh_w, const float* __restrict__ rflh_b,
    const float* __restrict__ rfrh_w, const float* __restrict__ rfrh_b,
    const float* __restrict__ ulh_w,  const float* __restrict__ ulh_b,
    const float* __restrict__ urh_w,  const float* __restrict__ urh_b,
    float* __restrict__ out)
{
    const int warp = (blockIdx.x * blockDim.x + threadIdx.x) >> 5;
    const int lane = threadIdx.x & 31;
    if (warp >= MEM) return;

    const size_t roff = (size_t)warp * NV4;
    const float4* __restrict__ m0 = (const float4*)ilh_w  + roff;
    const float4* __restrict__ m1 = (const float4*)irh_w  + roff;
    const float4* __restrict__ m2 = (const float4*)lflh_w + roff;
    const float4* __restrict__ m3 = (const float4*)lfrh_w + roff;
    const float4* __restrict__ m4 = (const float4*)rflh_w + roff;
    const float4* __restrict__ m5 = (const float4*)rfrh_w + roff;
    const float4* __restrict__ m6 = (const float4*)ulh_w  + roff;
    const float4* __restrict__ m7 = (const float4*)urh_w  + roff;
    const float4* __restrict__ la4 = (const float4*)g_la;
    const float4* __restrict__ ra4 = (const float4*)g_ra;

    float a0 = 0.f, a1 = 0.f, a2 = 0.f, a3 = 0.f;
    float a4 = 0.f, a5 = 0.f, a6 = 0.f, a7 = 0.f;
#pragma unroll 4
    for (int i = 0; i < ITERS; i++) {
        const int idx = i * 32 + lane;
        float4 l = la4[idx];
        float4 r = ra4[idx];
        float4 v0 = m0[idx];
        float4 v1 = m1[idx];
        float4 v2 = m2[idx];
        float4 v3 = m3[idx];
        float4 v4 = m4[idx];
        float4 v5 = m5[idx];
        float4 v6 = m6[idx];
        float4 v7 = m7[idx];
        a0 += dot4(v0, l);
        a1 += dot4(v1, r);
        a2 += dot4(v2, l);
        a3 += dot4(v3, r);
        a4 += dot4(v4, l);
        a5 += dot4(v5, r);
        a6 += dot4(v6, l);
        a7 += dot4(v7, r);
    }
    a0 = warp_sum(a0);
    a1 = warp_sum(a1);
    a2 = warp_sum(a2);
    a3 = warp_sum(a3);
    a4 = warp_sum(a4);
    a5 = warp_sum(a5);
    a6 = warp_sum(a6);
    a7 = warp_sum(a7);

    if (lane == 0) {
        const int j = warp;
        const float gi  = a0 + a1 + ilh_b[j]  + irh_b[j];
        const float glf = a2 + a3 + lflh_b[j] + lfrh_b[j];
        const float grf = a4 + a5 + rflh_b[j] + rfrh_b[j];
        const float gu  = a6 + a7 + ulh_b[j]  + urh_b[j];
        const float ig  = 1.0f / (1.0f + expf(-gi));
        const float lf  = 1.0f / (1.0f + expf(-glf));
        const float rf  = 1.0f / (1.0f + expf(-grf));
        const float u   = tanhf(gu);
        const float c   = ig * u + lf * lc[j] + rf * rc[j];
        out[j]       = c;
        out[MEM + j] = tanhf(c);
    }
}

// ---------------------------------------------------------------------------
// Input order (metadata): lc, lh, rc, rh, S, w, then (W, b) pairs for
// Wh, Us, ma, ilh, irh, lflh, lfrh, rflh, rfrh, ulh, urh.
// Output: c (2048 floats) followed by h (2048 floats).
// ---------------------------------------------------------------------------
extern "C" void kernel_launch(void* const* d_in, const int* in_sizes, int n_in,
                              void* d_out, int out_size)
{
    const float* lc = (const float*)d_in[0];
    const float* lh = (const float*)d_in[1];
    const float* rc = (const float*)d_in[2];
    const float* rh = (const float*)d_in[3];
    const float* S  = (const float*)d_in[4];
    const float* w  = (const float*)d_in[5];

    const float* Wh_w   = (const float*)d_in[6];
    const float* Wh_b   = (const float*)d_in[7];
    const float* Us_w   = (const float*)d_in[8];
    const float* Us_b   = (const float*)d_in[9];
    const float* ma_w   = (const float*)d_in[10];
    const float* ma_b   = (const float*)d_in[11];
    const float* ilh_w  = (const float*)d_in[12];
    const float* ilh_b  = (const float*)d_in[13];
    const float* irh_w  = (const float*)d_in[14];
    const float* irh_b  = (const float*)d_in[15];
    const float* lflh_w = (const float*)d_in[16];
    const float* lflh_b = (const float*)d_in[17];
    const float* lfrh_w = (const float*)d_in[18];
    const float* lfrh_b = (const float*)d_in[19];
    const float* rflh_w = (const float*)d_in[20];
    const float* rflh_b = (const float*)d_in[21];
    const float* rfrh_w = (const float*)d_in[22];
    const float* rfrh_b = (const float*)d_in[23];
    const float* ulh_w  = (const float*)d_in[24];
    const float* ulh_b  = (const float*)d_in[25];
    const float* urh_w  = (const float*)d_in[26];
    const float* urh_b  = (const float*)d_in[27];

    float* out = (float*)d_out;

    // 2048 warps -> 512 blocks of 128 threads
    k1_score<<<512, 128>>>(lh, rh, S, w, Wh_w, Wh_b, Us_w, Us_b, ma_w);
    k2_alpha<<<1, 1024>>>(ma_b);
    k3_gates<<<512, 128>>>(lc, rc,
                           ilh_w, ilh_b, irh_w, irh_b,
                           lflh_w, lflh_b, lfrh_w, lfrh_b,
                           rflh_w, rflh_b, rfrh_w, rfrh_b,
                           ulh_w, ulh_b, urh_w, urh_b,
                           out);
}

// round 2
// speedup vs baseline: 1.1420x; 1.1420x over previous
#include <cuda_runtime.h>
#include <math.h>

#define MEM 2048
#define NV4 (MEM / 4)          // float4 per row = 512

// Scratch (allocation-free: __device__ globals)
__device__ float g_sL[MEM];    // w[j] * m_left[j]
__device__ float g_sR[MEM];    // w[j] * m_right[j]
__device__ float g_pL[MEM];    // (ma @ lh)[j]
__device__ float g_pR[MEM];    // (ma @ rh)[j]
__device__ float g_la[MEM];
__device__ float g_ra[MEM];

__device__ __forceinline__ float warp_sum(float v) {
#pragma unroll
    for (int o = 16; o > 0; o >>= 1) v += __shfl_xor_sync(0xffffffffu, v, o);
    return v;
}

__device__ __forceinline__ float dot4(float4 a, float4 b) {
    return fmaf(a.x, b.x, fmaf(a.y, b.y, fmaf(a.z, b.z, a.w * b.w)));
}

// ---------------------------------------------------------------------------
// K1: attention scoring + hoisted ma matvecs.
// One BLOCK per output row j, 6 warps: (matrix, K-half) work items.
//   warps 0,1 -> Wh (dots with lh and rh), halves 0,1
//   warps 2,3 -> Us (dot with S)
//   warps 4,5 -> ma (dots with lh and rh)
// ---------------------------------------------------------------------------
__global__ void __launch_bounds__(192) k1_score(
    const float* __restrict__ lh, const float* __restrict__ rh,
    const float* __restrict__ S,  const float* __restrict__ w,
    const float* __restrict__ Wh_w, const float* __restrict__ Wh_b,
    const float* __restrict__ Us_w, const float* __restrict__ Us_b,
    const float* __restrict__ ma_w)
{
    const int row  = blockIdx.x;
    const int wid  = threadIdx.x >> 5;   // 0..5
    const int lane = threadIdx.x & 31;
    const int mat  = wid >> 1;           // 0=Wh, 1=Us, 2=ma
    const int half = wid & 1;

    __shared__ float sWL[2], sWR[2], sUS[2], sML[2], sMR[2];

    const float4* __restrict__ lh4 = (const float4*)lh;
    const float4* __restrict__ rh4 = (const float4*)rh;
    const float4* __restrict__ S4  = (const float4*)S;
    const int base_idx = half * (NV4 / 2) + lane;   // half*256 + lane

    if (mat == 0) {
        const float4* __restrict__ M = (const float4*)Wh_w + (size_t)row * NV4;
        float aL = 0.f, aR = 0.f;
#pragma unroll
        for (int i = 0; i < 8; i++) {
            const int idx = base_idx + i * 32;
            float4 m = M[idx];
            float4 l = lh4[idx];
            float4 r = rh4[idx];
            aL += dot4(m, l);
            aR += dot4(m, r);
        }
        aL = warp_sum(aL);
        aR = warp_sum(aR);
        if (lane == 0) { sWL[half] = aL; sWR[half] = aR; }
    } else if (mat == 1) {
        const float4* __restrict__ M = (const float4*)Us_w + (size_t)row * NV4;
        float aU = 0.f;
#pragma unroll
        for (int i = 0; i < 8; i++) {
            const int idx = base_idx + i * 32;
            aU += dot4(M[idx], S4[idx]);
        }
        aU = warp_sum(aU);
        if (lane == 0) sUS[half] = aU;
    } else {
        const float4* __restrict__ M = (const float4*)ma_w + (size_t)row * NV4;
        float aL = 0.f, aR = 0.f;
#pragma unroll
        for (int i = 0; i < 8; i++) {
            const int idx = base_idx + i * 32;
            float4 m = M[idx];
            float4 l = lh4[idx];
            float4 r = rh4[idx];
            aL += dot4(m, l);
            aR += dot4(m, r);
        }
        aL = warp_sum(aL);
        aR = warp_sum(aR);
        if (lane == 0) { sML[half] = aL; sMR[half] = aR; }
    }
    __syncthreads();

    if (threadIdx.x == 0) {
        const float aWL = sWL[0] + sWL[1];
        const float aWR = sWR[0] + sWR[1];
        const float aUS = sUS[0] + sUS[1];
        const float base = Wh_b[row] + Us_b[row];
        const float mL = tanhf(aWL + aUS + base);
        const float mR = tanhf(aWR + aUS + base);
        const float wj = w[row];
        g_sL[row] = wj * mL;
        g_sR[row] = wj * mR;
        g_pL[row] = sML[0] + sML[1];
        g_pR[row] = sMR[0] + sMR[1];
    }
}

// ---------------------------------------------------------------------------
// K2: reduce scores -> alphas -> la/ra. Single block (tiny).
// ---------------------------------------------------------------------------
__global__ void __launch_bounds__(1024) k2_alpha(const float* __restrict__ ma_b)
{
    __shared__ float sL[1024];
    __shared__ float sR[1024];
    __shared__ float s_aL, s_aR;
    const int t = threadIdx.x;

    sL[t] = g_sL[t] + g_sL[t + 1024];
    sR[t] = g_sR[t] + g_sR[t + 1024];
    __syncthreads();
#pragma unroll
    for (int s = 512; s > 0; s >>= 1) {
        if (t < s) { sL[t] += sL[t + s]; sR[t] += sR[t + s]; }
        __syncthreads();
    }
    if (t == 0) {
        const float eL = sL[0], eR = sR[0];
        const float inv = 1.0f / (eL + eR);
        s_aL = eL * inv;
        s_aR = eR * inv;
    }
    __syncthreads();
    const float aL = s_aL, aR = s_aR;

#pragma unroll
    for (int j = t; j < MEM; j += 1024) {
        const float b = ma_b[j];
        g_la[j] = tanhf(fmaf(aL, g_pL[j], b));
        g_ra[j] = tanhf(fmaf(aR, g_pR[j], b));
    }
}

// ---------------------------------------------------------------------------
// K3: all 8 gate matvecs + LSTM combine.
// One BLOCK per output element j, 8 warps: one warp per gate matrix.
// Even warps dot with la, odd warps dot with ra.
// ---------------------------------------------------------------------------
__global__ void __launch_bounds__(256) k3_gates(
    const float* __restrict__ lc, const float* __restrict__ rc,
    const float* __restrict__ ilh_w,  const float* __restrict__ ilh_b,
    const float* __restrict__ irh_w,  const float* __restrict__ irh_b,
    const float* __restrict__ lflh_w, const float* __restrict__ lflh_b,
    const float* __restrict__ lfrh_w, const float* __restrict__ lfrh_b,
    const float* __restrict__ rflh_w, const float* __restrict__ rflh_b,
    const float* __restrict__ rfrh_w, const float* __restrict__ rfrh_b,
    const float* __restrict__ ulh_w,  const float* __restrict__ ulh_b,
    const float* __restrict__ urh_w,  const float* __restrict__ urh_b,
    float* __restrict__ out)
{
    const int row  = blockIdx.x;
    const int wid  = threadIdx.x >> 5;   // 0..7 = gate index
    const int lane = threadIdx.x & 31;

    __shared__ float s_g[8];

    const float* mat;
    switch (wid) {
        case 0: mat = ilh_w;  break;
        case 1: mat = irh_w;  break;
        case 2: mat = lflh_w; break;
        case 3: mat = lfrh_w; break;
        case 4: mat = rflh_w; break;
        case 5: mat = rfrh_w; break;
        case 6: mat = ulh_w;  break;
        default: mat = urh_w; break;
    }
    const float4* __restrict__ M = (const float4*)mat + (size_t)row * NV4;
    const float4* __restrict__ V = (wid & 1) ? (const float4*)g_ra
                                             : (const float4*)g_la;

    float acc = 0.f;
#pragma unroll 8
    for (int i = 0; i < 16; i++) {
        const int idx = i * 32 + lane;
        acc += dot4(M[idx], V[idx]);
    }
    acc = warp_sum(acc);
    if (lane == 0) s_g[wid] = acc;
    __syncthreads();

    if (threadIdx.x == 0) {
        const int j = row;
        const float gi  = s_g[0] + s_g[1] + ilh_b[j]  + irh_b[j];
        const float glf = s_g[2] + s_g[3] + lflh_b[j] + lfrh_b[j];
        const float grf = s_g[4] + s_g[5] + rflh_b[j] + rfrh_b[j];
        const float gu  = s_g[6] + s_g[7] + ulh_b[j]  + urh_b[j];
        const float ig  = 1.0f / (1.0f + expf(-gi));
        const float lf  = 1.0f / (1.0f + expf(-glf));
        const float rf  = 1.0f / (1.0f + expf(-grf));
        const float u   = tanhf(gu);
        const float c   = ig * u + lf * lc[j] + rf * rc[j];
        out[j]       = c;
        out[MEM + j] = tanhf(c);
    }
}

// ---------------------------------------------------------------------------
// Input order (metadata): lc, lh, rc, rh, S, w, then (W, b) pairs for
// Wh, Us, ma, ilh, irh, lflh, lfrh, rflh, rfrh, ulh, urh.
// Output: c (2048 floats) followed by h (2048 floats).
// ---------------------------------------------------------------------------
extern "C" void kernel_launch(void* const* d_in, const int* in_sizes, int n_in,
                              void* d_out, int out_size)
{
    const float* lc = (const float*)d_in[0];
    const float* lh = (const float*)d_in[1];
    const float* rc = (const float*)d_in[2];
    const float* rh = (const float*)d_in[3];
    const float* S  = (const float*)d_in[4];
    const float* w  = (const float*)d_in[5];

    const float* Wh_w   = (const float*)d_in[6];
    const float* Wh_b   = (const float*)d_in[7];
    const float* Us_w   = (const float*)d_in[8];
    const float* Us_b   = (const float*)d_in[9];
    const float* ma_w   = (const float*)d_in[10];
    const float* ma_b   = (const float*)d_in[11];
    const float* ilh_w  = (const float*)d_in[12];
    const float* ilh_b  = (const float*)d_in[13];
    const float* irh_w  = (const float*)d_in[14];
    const float* irh_b  = (const float*)d_in[15];
    const float* lflh_w = (const float*)d_in[16];
    const float* lflh_b = (const float*)d_in[17];
    const float* lfrh_w = (const float*)d_in[18];
    const float* lfrh_b = (const float*)d_in[19];
    const float* rflh_w = (const float*)d_in[20];
    const float* rflh_b = (const float*)d_in[21];
    const float* rfrh_w = (const float*)d_in[22];
    const float* rfrh_b = (const float*)d_in[23];
    const float* ulh_w  = (const float*)d_in[24];
    const float* ulh_b  = (const float*)d_in[25];
    const float* urh_w  = (const float*)d_in[26];
    const float* urh_b  = (const float*)d_in[27];

    float* out = (float*)d_out;

    k1_score<<<MEM, 192>>>(lh, rh, S, w, Wh_w, Wh_b, Us_w, Us_b, ma_w);
    k2_alpha<<<1, 1024>>>(ma_b);
    k3_gates<<<MEM, 256>>>(lc, rc,
                           ilh_w, ilh_b, irh_w, irh_b,
                           lflh_w, lflh_b, lfrh_w, lfrh_b,
                           rflh_w, rflh_b, rfrh_w, rfrh_b,
                           ulh_w, ulh_b, urh_w, urh_b,
                           out);
}